// round 1
// baseline (speedup 1.0000x reference)
#include <cuda_runtime.h>
#include <cstdint>
#include <cstddef>

// ---------------- problem constants ----------------
#define Hd   1024
#define Bsz  32
#define Tlen 512
#define GH   (4*Hd)
#define NBLK 128      // recurrence blocks (one per SM, single wave)
#define HPB  8        // h columns per block
#define GPB  32       // gate columns per block (4 gates x HPB)

// ---------------- device scratch (no cudaMalloc allowed) ----------------
__device__ float g_xg[(size_t)Tlen * Bsz * GH];   // 256 MB: xg for current layer
__device__ float g_out0[(size_t)Tlen * Bsz * Hd]; // 64 MB: layer-0 hidden outputs
__device__ float g_h[Bsz * Hd];                   // current hidden state (tf32-rounded)
__device__ unsigned g_barcnt;
__device__ volatile unsigned g_bargen;

// ---------------- small helpers ----------------
__device__ __forceinline__ uint32_t f2tf(float x) {
    uint32_t r;
    asm("cvt.rna.tf32.f32 %0, %1;" : "=r"(r) : "f"(x));
    return r;
}
__device__ __forceinline__ float sigmoidf_(float x) {
    return 1.0f / (1.0f + __expf(-x));
}
__device__ __forceinline__ void cpasync16(float* s, const float* g) {
    uint32_t sa = (uint32_t)__cvta_generic_to_shared(s);
    asm volatile("cp.async.cg.shared.global [%0], [%1], 16;" :: "r"(sa), "l"(g));
}
__device__ __forceinline__ void cp_commit()  { asm volatile("cp.async.commit_group;"); }
__device__ __forceinline__ void cp_wait_1()  { asm volatile("cp.async.wait_group 1;"); }
__device__ __forceinline__ void cp_wait_0()  { asm volatile("cp.async.wait_group 0;"); }

__device__ __forceinline__ void mma_tf32(float* c, const uint32_t* a, uint32_t b0, uint32_t b1) {
    asm volatile(
        "mma.sync.aligned.m16n8k8.row.col.f32.tf32.tf32.f32 "
        "{%0,%1,%2,%3},{%4,%5,%6,%7},{%8,%9},{%0,%1,%2,%3};"
        : "+f"(c[0]), "+f"(c[1]), "+f"(c[2]), "+f"(c[3])
        : "r"(a[0]), "r"(a[1]), "r"(a[2]), "r"(a[3]), "r"(b0), "r"(b1));
}

// grid-wide sense-reversing barrier (all NBLK blocks are co-resident)
__device__ __forceinline__ void grid_barrier() {
    __syncthreads();
    if (threadIdx.x == 0) {
        unsigned gen = g_bargen;
        __threadfence();
        if (atomicAdd(&g_barcnt, 1u) == NBLK - 1) {
            g_barcnt = 0;
            __threadfence();
            g_bargen = gen + 1;
        } else {
            while (g_bargen == gen) { }
            __threadfence();
        }
    }
    __syncthreads();
}

// =====================================================================
// GEMM: C[M,N] = A[M,1024] @ B[N,1024]^T + bias[N]   (tf32 mma.sync)
// =====================================================================
#define BM 128
#define BN 64
#define BK 32
#define LDT (BK + 4)   // 36 floats: pad keeps 16B alignment, kills bank conflicts

__global__ void __launch_bounds__(256) gemm_bias_tf32(
    const float* __restrict__ A, const float* __restrict__ Bw,
    const float* __restrict__ bias, float* __restrict__ C, int M, int N)
{
    extern __shared__ float sm[];
    const int K = 1024;
    float* As = sm;                 // [2][BM][LDT]
    float* Bs = sm + 2 * BM * LDT;  // [2][BN][LDT]

    const int tid  = threadIdx.x;
    const int lane = tid & 31, wid = tid >> 5;
    const int wm = wid & 3, wn = wid >> 2;       // 4 x 2 warp grid, warp tile 32x32
    const int lr = lane >> 2, lc = lane & 3;
    const int bn = blockIdx.x, bm = blockIdx.y;

    const float* Ab = A  + (size_t)bm * BM * K;
    const float* Bb = Bw + (size_t)bn * BN * K;

    float acc[2][4][4];
    #pragma unroll
    for (int i = 0; i < 2; i++)
        #pragma unroll
        for (int j = 0; j < 4; j++)
            #pragma unroll
            for (int k = 0; k < 4; k++) acc[i][j][k] = 0.f;

    auto load_tiles = [&](int st, int kb) {
        float* ad = As + st * BM * LDT;
        #pragma unroll
        for (int i = 0; i < 4; i++) {
            int s = tid + i * 256;             // 1024 16B segments for A
            int row = s >> 3, sc = s & 7;
            cpasync16(ad + row * LDT + sc * 4, Ab + (size_t)row * K + kb * BK + sc * 4);
        }
        float* bd = Bs + st * BN * LDT;
        #pragma unroll
        for (int i = 0; i < 2; i++) {
            int s = tid + i * 256;             // 512 segments for B
            int row = s >> 3, sc = s & 7;
            cpasync16(bd + row * LDT + sc * 4, Bb + (size_t)row * K + kb * BK + sc * 4);
        }
    };

    load_tiles(0, 0);
    cp_commit();

    const int NKB = K / BK; // 32
    for (int kb = 0; kb < NKB; kb++) {
        if (kb + 1 < NKB) { load_tiles((kb + 1) & 1, kb + 1); cp_commit(); cp_wait_1(); }
        else              { cp_wait_0(); }
        __syncthreads();

        const float* as = As + (kb & 1) * BM * LDT + (wm * 32 + lr) * LDT + lc;
        const float* bs = Bs + (kb & 1) * BN * LDT + (wn * 32 + lr) * LDT + lc;

        #pragma unroll
        for (int kk = 0; kk < 4; kk++) {
            uint32_t a[2][4];
            #pragma unroll
            for (int mt = 0; mt < 2; mt++) {
                const float* ap = as + mt * 16 * LDT + kk * 8;
                a[mt][0] = f2tf(ap[0]);
                a[mt][1] = f2tf(ap[8 * LDT]);
                a[mt][2] = f2tf(ap[4]);
                a[mt][3] = f2tf(ap[8 * LDT + 4]);
            }
            #pragma unroll
            for (int nt = 0; nt < 4; nt++) {
                const float* bp = bs + nt * 8 * LDT + kk * 8;
                uint32_t b0 = f2tf(bp[0]);
                uint32_t b1 = f2tf(bp[4]);
                #pragma unroll
                for (int mt = 0; mt < 2; mt++)
                    mma_tf32(acc[mt][nt], a[mt], b0, b1);
            }
        }
        __syncthreads();
    }

    // epilogue: + bias, store fp32
    #pragma unroll
    for (int mt = 0; mt < 2; mt++) {
        int m0 = bm * BM + wm * 32 + mt * 16 + lr;
        #pragma unroll
        for (int nt = 0; nt < 4; nt++) {
            int n0 = bn * BN + wn * 32 + nt * 8 + 2 * lc;
            float bv0 = bias[n0], bv1 = bias[n0 + 1];
            float2 v0 = make_float2(acc[mt][nt][0] + bv0, acc[mt][nt][1] + bv1);
            float2 v1 = make_float2(acc[mt][nt][2] + bv0, acc[mt][nt][3] + bv1);
            *(float2*)(C + (size_t)m0 * N + n0)       = v0;
            *(float2*)(C + (size_t)(m0 + 8) * N + n0) = v1;
        }
    }
}

// =====================================================================
// Persistent subLSTM recurrence.
// Block b owns h columns [8b, 8b+8) -> gate columns {g*1024 + 8b + j}.
// R slice (tf32-rounded) resident in smem; h broadcast per step via
// cp.async.cg (L1 bypass); grid barrier per timestep.
// =====================================================================
#define LDR (Hd + 4)    // 1028
#define LDH (128 + 4)   // 132

__device__ __forceinline__ void load_h_chunk(float* Hs, int buf, int ch, int tid) {
    float* dst = Hs + buf * Bsz * LDH;
    const float* src = g_h + ch * 128;
    #pragma unroll
    for (int i = 0; i < 4; i++) {
        int s = tid + i * 256;            // 1024 16B segments (32 rows x 32)
        int row = s >> 5, sc = s & 31;
        cpasync16(dst + row * LDH + sc * 4, src + (size_t)row * Hd + sc * 4);
    }
}

__global__ void __launch_bounds__(256, 1) sublstm_rec(
    const float* __restrict__ xg, const float* __restrict__ R,
    const float* __restrict__ bh, const float* __restrict__ h0,
    const float* __restrict__ c0, float* __restrict__ out,
    float* __restrict__ hT, float* __restrict__ cT)
{
    extern __shared__ float sm[];
    float* Rs = sm;                    // [32][LDR]
    float* Hs = Rs + GPB * LDR;        // [2][32][LDH]
    float* Gs = Hs + 2 * Bsz * LDH;    // [32][33] sigmoid(gates), indexed [n][m]

    const int tid  = threadIdx.x;
    const int lane = tid & 31, wid = tid >> 5;
    const int bid  = blockIdx.x;
    const int lr = lane >> 2, lc = lane & 3;
    const int wm = wid & 1, wn = wid >> 1;      // 2(M) x 4(N) warp tiles of 16x8

    // Load R slice into smem, rna-rounded to tf32 so mma reads need no cvt.
    for (int i = tid; i < GPB * Hd; i += 256) {
        int n = i >> 10, k = i & (Hd - 1);
        int gr = (n >> 3) * Hd + bid * HPB + (n & 7);
        Rs[n * LDR + k] = __uint_as_float(f2tf(R[(size_t)gr * Hd + k]));
    }

    // per-thread cell state: thread -> (batch m, local col jl)
    const int m  = tid >> 3;
    const int jl = tid & 7;
    const int jg = bid * HPB + jl;
    float c = c0[m * Hd + jg];
    g_h[m * Hd + jg] = __uint_as_float(f2tf(h0[m * Hd + jg]));

    // mma fragment coordinates (fixed across steps)
    const int r0 = wm * 16 + lr, r1 = r0 + 8;           // batch rows
    const int n0 = wn * 8 + 2 * lc, n1 = n0 + 1;        // local gate cols
    const int gr0 = (n0 >> 3) * Hd + bid * HPB + (n0 & 7);
    const int gr1 = (n1 >> 3) * Hd + bid * HPB + (n1 & 7);
    const float bh0v = bh[gr0], bh1v = bh[gr1];

    grid_barrier();   // Rs + g_h init visible everywhere

    for (int t = 0; t < Tlen; t++) {
        // prefetch this step's xg contributions (ready long before epilogue)
        const size_t xb = (size_t)t * Bsz * GH;
        float x00 = xg[xb + (size_t)r0 * GH + gr0];
        float x01 = xg[xb + (size_t)r0 * GH + gr1];
        float x10 = xg[xb + (size_t)r1 * GH + gr0];
        float x11 = xg[xb + (size_t)r1 * GH + gr1];

        float acc[4] = {0.f, 0.f, 0.f, 0.f};

        load_h_chunk(Hs, 0, 0, tid);
        cp_commit();
        #pragma unroll 1
        for (int ch = 0; ch < 8; ch++) {
            if (ch < 7) { load_h_chunk(Hs, (ch + 1) & 1, ch + 1, tid); cp_commit(); cp_wait_1(); }
            else        { cp_wait_0(); }
            __syncthreads();
            const float* hp  = Hs + (ch & 1) * Bsz * LDH;
            const float* ap0 = hp + r0 * LDH + lc;
            const float* ap1 = hp + r1 * LDH + lc;
            const float* bp  = Rs + (wn * 8 + lr) * LDR + ch * 128 + lc;
            #pragma unroll
            for (int kk = 0; kk < 16; kk++) {
                uint32_t a[4];
                a[0] = __float_as_uint(ap0[kk * 8]);
                a[1] = __float_as_uint(ap1[kk * 8]);
                a[2] = __float_as_uint(ap0[kk * 8 + 4]);
                a[3] = __float_as_uint(ap1[kk * 8 + 4]);
                uint32_t b0 = __float_as_uint(bp[kk * 8]);
                uint32_t b1 = __float_as_uint(bp[kk * 8 + 4]);
                mma_tf32(acc, a, b0, b1);
            }
            __syncthreads();
        }

        // gates = sigmoid(acc + xg + bh), routed through smem to (m,j) layout
        Gs[n0 * 33 + r0] = sigmoidf_(acc[0] + x00 + bh0v);
        Gs[n1 * 33 + r0] = sigmoidf_(acc[1] + x01 + bh1v);
        Gs[n0 * 33 + r1] = sigmoidf_(acc[2] + x10 + bh0v);
        Gs[n1 * 33 + r1] = sigmoidf_(acc[3] + x11 + bh1v);
        __syncthreads();

        float ig = Gs[jl * 33 + m];
        float og = Gs[(8  + jl) * 33 + m];
        float zg = Gs[(16 + jl) * 33 + m];
        float fg = Gs[(24 + jl) * 33 + m];
        c = c * fg + zg - ig;                 // subtractive cell update
        float h = sigmoidf_(c) - og;          // subtractive output

        out[(size_t)t * Bsz * Hd + m * Hd + jg] = h;          // fp32 exact
        g_h[m * Hd + jg] = __uint_as_float(f2tf(h));          // tf32 for next mma
        if (t == Tlen - 1) {
            hT[m * Hd + jg] = h;
            cT[m * Hd + jg] = c;
        }
        __threadfence();
        grid_barrier();
    }
}

// =====================================================================
// launch
// =====================================================================
extern "C" void kernel_launch(void* const* d_in, const int* in_sizes, int n_in,
                              void* d_out, int out_size)
{
    const float* x   = (const float*)d_in[0];
    const float* h0  = (const float*)d_in[1];
    const float* c0  = (const float*)d_in[2];
    const float* W0  = (const float*)d_in[3];
    const float* R0  = (const float*)d_in[4];
    const float* bi0 = (const float*)d_in[5];
    const float* bh0 = (const float*)d_in[6];
    const float* W1  = (const float*)d_in[7];
    const float* R1  = (const float*)d_in[8];
    const float* bi1 = (const float*)d_in[9];
    const float* bh1 = (const float*)d_in[10];

    float* out = (float*)d_out;                       // [T,B,H]
    float* hTs = out + (size_t)Tlen * Bsz * Hd;       // [2,B,H]
    float* cTs = hTs + 2 * (size_t)Bsz * Hd;          // [2,B,H]

    float *xg_p, *o0_p;
    cudaGetSymbolAddress((void**)&xg_p, g_xg);
    cudaGetSymbolAddress((void**)&o0_p, g_out0);

    const int SMEM_G = 2 * (BM + BN) * LDT * (int)sizeof(float);                   // 55296
    const int SMEM_R = (GPB * LDR + 2 * Bsz * LDH + 32 * 33) * (int)sizeof(float); // 169600
    cudaFuncSetAttribute(gemm_bias_tf32, cudaFuncAttributeMaxDynamicSharedMemorySize, SMEM_G);
    cudaFuncSetAttribute(sublstm_rec,   cudaFuncAttributeMaxDynamicSharedMemorySize, SMEM_R);

    dim3 gg(4096 / BN, (Tlen * Bsz) / BM);  // (64, 128)

    // layer 0
    gemm_bias_tf32<<<gg, 256, SMEM_G>>>(x, W0, bi0, xg_p, Tlen * Bsz, GH);
    sublstm_rec<<<NBLK, 256, SMEM_R>>>(xg_p, R0, bh0, h0, c0, o0_p, hTs, cTs);
    // layer 1
    gemm_bias_tf32<<<gg, 256, SMEM_G>>>(o0_p, W1, bi1, xg_p, Tlen * Bsz, GH);
    sublstm_rec<<<NBLK, 256, SMEM_R>>>(xg_p, R1, bh1, h0 + Bsz * Hd, c0 + Bsz * Hd,
                                       out, hTs + Bsz * Hd, cTs + Bsz * Hd);
}

// round 3
// speedup vs baseline: 1.6003x; 1.6003x over previous
#include <cuda_runtime.h>
#include <cstdint>
#include <cstddef>

// ---------------- problem constants ----------------
#define Hd   1024
#define Bsz  32
#define Tlen 512
#define GH   (4*Hd)
#define NBLK 128      // recurrence blocks (one per SM, single wave)
#define HPB  8        // h columns per block
#define LDP  36       // Gpart padded stride (conflict-free for our patterns)

// ---------------- device scratch (no cudaMalloc allowed) ----------------
__device__ float g_xg[(size_t)Tlen * Bsz * GH];   // 256 MB: xg for current layer
__device__ float g_a4[(size_t)Tlen * Bsz * Hd];   // 64 MB: tf32-rounded GEMM A
__device__ float g_w4[2 * (size_t)GH * Hd];       // 32 MB: tf32-rounded W0|W1
__device__ float g_h[Bsz * Hd];                   // current hidden state (tf32-rounded)
__device__ unsigned g_barcnt;
__device__ volatile unsigned g_bargen;

// ---------------- small helpers ----------------
__device__ __forceinline__ uint32_t f2tf(float x) {
    uint32_t r;
    asm("cvt.rna.tf32.f32 %0, %1;" : "=r"(r) : "f"(x));
    return r;
}
__device__ __forceinline__ float sigmoidf_(float x) {
    return 1.0f / (1.0f + __expf(-x));
}
__device__ __forceinline__ void cpasync16(float* s, const float* g) {
    uint32_t sa = (uint32_t)__cvta_generic_to_shared(s);
    asm volatile("cp.async.cg.shared.global [%0], [%1], 16;" :: "r"(sa), "l"(g));
}
__device__ __forceinline__ void cp_commit()  { asm volatile("cp.async.commit_group;"); }
__device__ __forceinline__ void cp_wait_1()  { asm volatile("cp.async.wait_group 1;"); }
__device__ __forceinline__ void cp_wait_0()  { asm volatile("cp.async.wait_group 0;"); }

__device__ __forceinline__ void mma_tf32(float* c, uint32_t a0, uint32_t a1,
                                         uint32_t a2, uint32_t a3,
                                         uint32_t b0, uint32_t b1) {
    asm volatile(
        "mma.sync.aligned.m16n8k8.row.col.f32.tf32.tf32.f32 "
        "{%0,%1,%2,%3},{%4,%5,%6,%7},{%8,%9},{%0,%1,%2,%3};"
        : "+f"(c[0]), "+f"(c[1]), "+f"(c[2]), "+f"(c[3])
        : "r"(a0), "r"(a1), "r"(a2), "r"(a3), "r"(b0), "r"(b1));
}

// grid-wide sense-reversing barrier (all NBLK blocks co-resident).
__device__ __forceinline__ void grid_barrier() {
    __syncthreads();
    if (threadIdx.x == 0) {
        unsigned gen = g_bargen;
        __threadfence();
        if (atomicAdd(&g_barcnt, 1u) == NBLK - 1) {
            g_barcnt = 0;
            __threadfence();
            g_bargen = gen + 1;
        } else {
            while (g_bargen == gen) { __nanosleep(64); }
            __threadfence();
        }
    }
    __syncthreads();
}

// =====================================================================
// round-to-tf32 copy (pre-pass so GEMM needs no cvt in its hot loop)
// =====================================================================
__global__ void __launch_bounds__(256) round_tf32_kernel(
    const float* __restrict__ src, float* __restrict__ dst, int n4)
{
    int i = blockIdx.x * blockDim.x + threadIdx.x;
    int stride = gridDim.x * blockDim.x;
    for (; i < n4; i += stride) {
        float4 v = ((const float4*)src)[i];
        v.x = __uint_as_float(f2tf(v.x));
        v.y = __uint_as_float(f2tf(v.y));
        v.z = __uint_as_float(f2tf(v.z));
        v.w = __uint_as_float(f2tf(v.w));
        ((float4*)dst)[i] = v;
    }
}

// =====================================================================
// GEMM: C[M,N] = A[M,1024] @ B[N,1024]^T + bias1[N] + bias2[N]
// A, B pre-rounded to tf32 (bit-exact reinterpret in hot loop).
// =====================================================================
#define BM 128
#define BN 64
#define BK 32
#define LDT (BK + 4)

__global__ void __launch_bounds__(256) gemm_bias_tf32(
    const float* __restrict__ A, const float* __restrict__ Bw,
    const float* __restrict__ bias1, const float* __restrict__ bias2,
    float* __restrict__ C, int M, int N)
{
    extern __shared__ float sm[];
    const int K = 1024;
    float* As = sm;                 // [2][BM][LDT]
    float* Bs = sm + 2 * BM * LDT;  // [2][BN][LDT]

    const int tid  = threadIdx.x;
    const int lane = tid & 31, wid = tid >> 5;
    const int wm = wid & 3, wn = wid >> 2;       // 4 x 2 warp grid, warp tile 32x32
    const int lr = lane >> 2, lc = lane & 3;
    const int bn = blockIdx.x, bm = blockIdx.y;

    const float* Ab = A  + (size_t)bm * BM * K;
    const float* Bb = Bw + (size_t)bn * BN * K;

    float acc[2][4][4];
    #pragma unroll
    for (int i = 0; i < 2; i++)
        #pragma unroll
        for (int j = 0; j < 4; j++)
            #pragma unroll
            for (int k = 0; k < 4; k++) acc[i][j][k] = 0.f;

    auto load_tiles = [&](int st, int kb) {
        float* ad = As + st * BM * LDT;
        #pragma unroll
        for (int i = 0; i < 4; i++) {
            int s = tid + i * 256;
            int row = s >> 3, sc = s & 7;
            cpasync16(ad + row * LDT + sc * 4, Ab + (size_t)row * K + kb * BK + sc * 4);
        }
        float* bd = Bs + st * BN * LDT;
        #pragma unroll
        for (int i = 0; i < 2; i++) {
            int s = tid + i * 256;
            int row = s >> 3, sc = s & 7;
            cpasync16(bd + row * LDT + sc * 4, Bb + (size_t)row * K + kb * BK + sc * 4);
        }
    };

    load_tiles(0, 0);
    cp_commit();

    const int NKB = K / BK; // 32
    for (int kb = 0; kb < NKB; kb++) {
        if (kb + 1 < NKB) { load_tiles((kb + 1) & 1, kb + 1); cp_commit(); cp_wait_1(); }
        else              { cp_wait_0(); }
        __syncthreads();

        const float* as = As + (kb & 1) * BM * LDT + (wm * 32 + lr) * LDT + lc;
        const float* bs = Bs + (kb & 1) * BN * LDT + (wn * 32 + lr) * LDT + lc;

        #pragma unroll
        for (int kk = 0; kk < 4; kk++) {
            uint32_t a[2][4];
            #pragma unroll
            for (int mt = 0; mt < 2; mt++) {
                const float* ap = as + mt * 16 * LDT + kk * 8;
                a[mt][0] = __float_as_uint(ap[0]);
                a[mt][1] = __float_as_uint(ap[8 * LDT]);
                a[mt][2] = __float_as_uint(ap[4]);
                a[mt][3] = __float_as_uint(ap[8 * LDT + 4]);
            }
            #pragma unroll
            for (int nt = 0; nt < 4; nt++) {
                const float* bp = bs + nt * 8 * LDT + kk * 8;
                uint32_t b0 = __float_as_uint(bp[0]);
                uint32_t b1 = __float_as_uint(bp[4]);
                #pragma unroll
                for (int mt = 0; mt < 2; mt++)
                    mma_tf32(acc[mt][nt], a[mt][0], a[mt][1], a[mt][2], a[mt][3], b0, b1);
            }
        }
        __syncthreads();
    }

    #pragma unroll
    for (int mt = 0; mt < 2; mt++) {
        int m0 = bm * BM + wm * 32 + mt * 16 + lr;
        #pragma unroll
        for (int nt = 0; nt < 4; nt++) {
            int n0 = bn * BN + wn * 32 + nt * 8 + 2 * lc;
            float bv0 = bias1[n0] + bias2[n0];
            float bv1 = bias1[n0 + 1] + bias2[n0 + 1];
            float2 v0 = make_float2(acc[mt][nt][0] + bv0, acc[mt][nt][1] + bv1);
            float2 v1 = make_float2(acc[mt][nt][2] + bv0, acc[mt][nt][3] + bv1);
            *(float2*)(C + (size_t)m0 * N + n0)       = v0;
            *(float2*)(C + (size_t)(m0 + 8) * N + n0) = v1;
        }
    }
}

// =====================================================================
// Persistent subLSTM recurrence (register-resident R).
//
// Block b owns h columns [8b, 8b+8) -> 32 gate columns (4 gates x 8).
// 8 warps: warp kw = K-split slice [kw*128, kw*128+128). Each warp computes
// the full 32(batch) x 32(gate) tile over its K-slice with R held entirely
// in registers (tf32, loaded once). h fragments come straight from global
// memory via __ldcg float4 (L1-bypassed). K is permuted inside each 16-col
// group so the tf32 fragment layout matches 16B vectors; the same
// permutation is applied to R, so dot products are unchanged.
// Partial sums reduced across warps through static smem.
// round_output: store tf32-rounded h to out (used when out feeds layer-1 GEMM).
// =====================================================================
__global__ void __launch_bounds__(256, 1) sublstm_rec(
    const float* __restrict__ xg, const float* __restrict__ R,
    const float* __restrict__ h0, const float* __restrict__ c0,
    float* __restrict__ out, float* __restrict__ hT, float* __restrict__ cT,
    int round_output)
{
    __shared__ float Gpart[8 * 32 * LDP];   // 36,864 B

    const int tid  = threadIdx.x;
    const int lane = tid & 31;
    const int kw   = tid >> 5;              // K-split index 0..7
    const int lr   = lane >> 2, lc = lane & 3;
    const int bid  = blockIdx.x;

    // ---- load R slice into registers (once), tf32 + K-permutation ----
    uint32_t b[16][4][2];
    #pragma unroll
    for (int f = 0; f < 16; f++) {
        const int kb = kw * 128 + (f >> 1) * 16;
        const int p  = f & 1;
        #pragma unroll
        for (int nt = 0; nt < 4; nt++) {
            const int gr = nt * Hd + bid * HPB + lr;   // global gate row
            const float2 rv = *(const float2*)(R + (size_t)gr * Hd + kb + 4 * lc + 2 * p);
            b[f][nt][0] = f2tf(rv.x);
            b[f][nt][1] = f2tf(rv.y);
        }
    }

    // ---- per-thread cell state: thread -> (batch m, local col jl) ----
    const int m  = tid >> 3;
    const int jl = tid & 7;
    const int jg = bid * HPB + jl;
    float c = c0[m * Hd + jg];
    __stcg(&g_h[m * Hd + jg], __uint_as_float(f2tf(h0[m * Hd + jg])));

    // xg prefetch for step 0 (bh already folded into xg by the GEMM bias)
    float xv0 = __ldg(&xg[(size_t)m * GH + 0 * Hd + jg]);
    float xv1 = __ldg(&xg[(size_t)m * GH + 1 * Hd + jg]);
    float xv2 = __ldg(&xg[(size_t)m * GH + 2 * Hd + jg]);
    float xv3 = __ldg(&xg[(size_t)m * GH + 3 * Hd + jg]);

    grid_barrier();   // g_h init visible everywhere

    const float* gh0 = g_h + (size_t)lr * Hd + kw * 128 + 4 * lc;

    for (int t = 0; t < Tlen; t++) {
        float acc[2][4][4];
        #pragma unroll
        for (int i = 0; i < 2; i++)
            #pragma unroll
            for (int j = 0; j < 4; j++)
                #pragma unroll
                for (int k = 0; k < 4; k++) acc[i][j][k] = 0.f;

        #pragma unroll
        for (int grp = 0; grp < 8; grp++) {
            const float* hp = gh0 + grp * 16;
            float4 v[2][2];                       // [mf][half]: rows mf*16+lr, +8
            v[0][0] = __ldcg((const float4*)(hp));
            v[0][1] = __ldcg((const float4*)(hp +  8 * Hd));
            v[1][0] = __ldcg((const float4*)(hp + 16 * Hd));
            v[1][1] = __ldcg((const float4*)(hp + 24 * Hd));
            #pragma unroll
            for (int p = 0; p < 2; p++) {
                const int f = grp * 2 + p;
                uint32_t a[2][4];
                #pragma unroll
                for (int mf = 0; mf < 2; mf++) {
                    const float* lo = (const float*)&v[mf][0];
                    const float* hi = (const float*)&v[mf][1];
                    a[mf][0] = __float_as_uint(lo[2 * p]);
                    a[mf][1] = __float_as_uint(hi[2 * p]);
                    a[mf][2] = __float_as_uint(lo[2 * p + 1]);
                    a[mf][3] = __float_as_uint(hi[2 * p + 1]);
                }
                #pragma unroll
                for (int nt = 0; nt < 4; nt++)
                    #pragma unroll
                    for (int mf = 0; mf < 2; mf++)
                        mma_tf32(acc[mf][nt], a[mf][0], a[mf][1], a[mf][2], a[mf][3],
                                 b[f][nt][0], b[f][nt][1]);
            }
        }

        // ---- cross-warp K reduction via smem ----
        #pragma unroll
        for (int mf = 0; mf < 2; mf++)
            #pragma unroll
            for (int nt = 0; nt < 4; nt++)
                #pragma unroll
                for (int cc = 0; cc < 4; cc++) {
                    const int r = mf * 16 + lr + ((cc >> 1) << 3);
                    const int n = nt * 8 + 2 * lc + (cc & 1);
                    Gpart[(kw * 32 + n) * LDP + r] = acc[mf][nt][cc];
                }
        __syncthreads();

        // ---- epilogue: thread (m, jl) computes its cell ----
        float pre[4];
        #pragma unroll
        for (int g = 0; g < 4; g++) {
            const int n = g * 8 + jl;
            float s = Gpart[(0 * 32 + n) * LDP + m];
            #pragma unroll
            for (int k = 1; k < 8; k++) s += Gpart[(k * 32 + n) * LDP + m];
            pre[g] = s;
        }
        const float ig = sigmoidf_(pre[0] + xv0);
        const float og = sigmoidf_(pre[1] + xv1);
        const float zg = sigmoidf_(pre[2] + xv2);
        const float fg = sigmoidf_(pre[3] + xv3);
        c = c * fg + zg - ig;                 // subtractive cell update
        const float h = sigmoidf_(c) - og;    // subtractive output
        const float hr = __uint_as_float(f2tf(h));

        out[(size_t)t * Bsz * Hd + m * Hd + jg] = round_output ? hr : h;
        __stcg(&g_h[m * Hd + jg], hr);
        if (t == Tlen - 1) {
            hT[m * Hd + jg] = h;
            cT[m * Hd + jg] = c;
        }

        // prefetch next step's xg while the barrier drains
        const int tn = (t + 1 < Tlen) ? t + 1 : t;
        const size_t xb = (size_t)tn * Bsz * GH + (size_t)m * GH + jg;
        xv0 = __ldg(&xg[xb + 0 * Hd]);
        xv1 = __ldg(&xg[xb + 1 * Hd]);
        xv2 = __ldg(&xg[xb + 2 * Hd]);
        xv3 = __ldg(&xg[xb + 3 * Hd]);

        grid_barrier();
    }
}

// =====================================================================
// launch
// =====================================================================
extern "C" void kernel_launch(void* const* d_in, const int* in_sizes, int n_in,
                              void* d_out, int out_size)
{
    const float* x   = (const float*)d_in[0];
    const float* h0  = (const float*)d_in[1];
    const float* c0  = (const float*)d_in[2];
    const float* W0  = (const float*)d_in[3];
    const float* R0  = (const float*)d_in[4];
    const float* bi0 = (const float*)d_in[5];
    const float* bh0 = (const float*)d_in[6];
    const float* W1  = (const float*)d_in[7];
    const float* R1  = (const float*)d_in[8];
    const float* bi1 = (const float*)d_in[9];
    const float* bh1 = (const float*)d_in[10];

    float* out = (float*)d_out;                       // [T,B,H]
    float* hTs = out + (size_t)Tlen * Bsz * Hd;       // [2,B,H]
    float* cTs = hTs + 2 * (size_t)Bsz * Hd;          // [2,B,H]

    float *xg_p, *a4_p, *w4_p;
    cudaGetSymbolAddress((void**)&xg_p, g_xg);
    cudaGetSymbolAddress((void**)&a4_p, g_a4);
    cudaGetSymbolAddress((void**)&w4_p, g_w4);

    const int SMEM_G = 2 * (BM + BN) * LDT * (int)sizeof(float);
    cudaFuncSetAttribute(gemm_bias_tf32, cudaFuncAttributeMaxDynamicSharedMemorySize, SMEM_G);

    dim3 gg(GH / BN, (Tlen * Bsz) / BM);  // (64, 128)
    const int MR = Tlen * Bsz * Hd / 4;   // float4 count for A-size arrays
    const int WR = GH * Hd / 4;           // float4 count for one W

    // pre-round weights (both layers) and layer-0 A
    round_tf32_kernel<<<512, 256>>>(W0, w4_p, WR);
    round_tf32_kernel<<<512, 256>>>(W1, w4_p + (size_t)GH * Hd, WR);
    round_tf32_kernel<<<1024, 256>>>(x, a4_p, MR);

    // layer 0: GEMM -> recurrence (writes tf32-rounded hidden stream into g_a4,
    // which is exactly the A operand layer-1's GEMM needs)
    gemm_bias_tf32<<<gg, 256, SMEM_G>>>(a4_p, w4_p, bi0, bh0, xg_p, Tlen * Bsz, GH);
    sublstm_rec<<<NBLK, 256>>>(xg_p, R0, h0, c0, a4_p, hTs, cTs, 1);

    // layer 1
    gemm_bias_tf32<<<gg, 256, SMEM_G>>>(a4_p, w4_p + (size_t)GH * Hd, bi1, bh1,
                                        xg_p, Tlen * Bsz, GH);
    sublstm_rec<<<NBLK, 256>>>(xg_p, R1, h0 + Bsz * Hd, c0 + Bsz * Hd,
                               out, hTs + Bsz * Hd, cTs + Bsz * Hd, 0);
}